// round 8
// baseline (speedup 1.0000x reference)
#include <cuda_runtime.h>
#include <cuda_bf16.h>
#include <cstdint>

// Problem constants
#define B_SZ   4096
#define DIN    768
#define DOUT   512
#define Q_SZ   64
#define H1_SZ  32
#define H2_SZ  64
#define EPS    1e-5f

// GEMM1 split-K: K' = 3 * DIN, split across 2 CTAs in z
#define KSPLIT (3 * DIN)          // 2304
#define KC     64
#define NCHH   (KSPLIT / KC / 2)  // 18 chunks per K-half
#define GS     3                  // pipeline stages
#define TILEB  16384              // one 128x64 bf16 tile
#define STAGEB (2 * TILEB)

// ---------------------------------------------------------------------------
// Static device scratch
// ---------------------------------------------------------------------------
__device__ __align__(256) float          g_xp[2][B_SZ * DOUT];          // 16 MB partials
__device__ __align__(256) __nv_bfloat16  g_A[B_SZ * KSPLIT];            // 18.9 MB
__device__ __align__(256) __nv_bfloat16  g_Bt[DOUT * KSPLIT];           // 2.36 MB

// ---------------------------------------------------------------------------
// Helpers
// ---------------------------------------------------------------------------
__device__ __forceinline__ uint32_t smem_u32(const void* p) {
    uint32_t a;
    asm("{ .reg .u64 t; cvta.to.shared.u64 t, %1; cvt.u32.u64 %0, t; }"
        : "=r"(a) : "l"(p));
    return a;
}
__device__ __forceinline__ uint32_t swz(uint32_t off) {
    return off ^ ((off >> 3) & 0x70);
}
__device__ __forceinline__ void cpasync16(uint32_t dst, const void* src) {
    asm volatile("cp.async.cg.shared.global [%0], [%1], 16;"
                 :: "r"(dst), "l"(src) : "memory");
}
__device__ __forceinline__ void ldsm_x4(uint32_t* r, uint32_t addr) {
    asm volatile("ldmatrix.sync.aligned.m8n8.x4.shared.b16 {%0,%1,%2,%3}, [%4];"
                 : "=r"(r[0]), "=r"(r[1]), "=r"(r[2]), "=r"(r[3]) : "r"(addr));
}
__device__ __forceinline__ void mma16816(float* d, const uint32_t* a, const uint32_t* b) {
    asm volatile(
        "mma.sync.aligned.m16n8k16.row.col.f32.bf16.bf16.f32 "
        "{%0,%1,%2,%3}, {%4,%5,%6,%7}, {%8,%9}, {%0,%1,%2,%3};"
        : "+f"(d[0]), "+f"(d[1]), "+f"(d[2]), "+f"(d[3])
        : "r"(a[0]), "r"(a[1]), "r"(a[2]), "r"(a[3]), "r"(b[0]), "r"(b[1]));
}

// ---- packed f32x2 ----
__device__ __forceinline__ uint64_t pk2(float x, float y) {
    uint64_t r; asm("mov.b64 %0,{%1,%2};" : "=l"(r) : "f"(x), "f"(y)); return r;
}
__device__ __forceinline__ void upk2(uint64_t v, float& x, float& y) {
    asm("mov.b64 {%0,%1},%2;" : "=f"(x), "=f"(y) : "l"(v));
}
__device__ __forceinline__ uint64_t fma2(uint64_t a, uint64_t b, uint64_t c) {
    uint64_t d; asm("fma.rn.f32x2 %0,%1,%2,%3;" : "=l"(d) : "l"(a), "l"(b), "l"(c));
    return d;
}
__device__ __forceinline__ uint64_t add2(uint64_t a, uint64_t b) {
    uint64_t d; asm("add.rn.f32x2 %0,%1,%2;" : "=l"(d) : "l"(a), "l"(b));
    return d;
}
__device__ __forceinline__ uint64_t abs2(uint64_t a) {
    uint64_t d; asm("and.b64 %0,%1,0x7FFFFFFF7FFFFFFF;" : "=l"(d) : "l"(a));
    return d;
}

// ---------------------------------------------------------------------------
// Conversions (fp32 -> bf16 hi/lo, 3-term fold into K)
// ---------------------------------------------------------------------------
__global__ void __launch_bounds__(256)
conv_x(const float* __restrict__ x, __nv_bfloat16* __restrict__ A)
{
    const int row = blockIdx.x;
    const float* xr = x + (long)row * DIN;
    __nv_bfloat16* Ar = A + (long)row * KSPLIT;
    #pragma unroll
    for (int i = 0; i < 3; i++) {
        const int k = threadIdx.x + i * 256;
        const float v = xr[k];
        const __nv_bfloat16 hi = __float2bfloat16(v);
        const __nv_bfloat16 lo = __float2bfloat16(v - __bfloat162float(hi));
        Ar[k]            = hi;
        Ar[k + DIN]      = hi;
        Ar[k + 2 * DIN]  = lo;
    }
}

__global__ void __launch_bounds__(256)
conv_w(const float* __restrict__ wp, __nv_bfloat16* __restrict__ Bt)
{
    __shared__ float t[32][33];
    const int k0 = blockIdx.x * 32, n0 = blockIdx.y * 32;
    const int tx = threadIdx.x & 31;
    const int ty = threadIdx.x >> 5;
    #pragma unroll
    for (int dy = 0; dy < 32; dy += 8)
        t[ty + dy][tx] = wp[(long)(k0 + ty + dy) * DOUT + n0 + tx];
    __syncthreads();
    #pragma unroll
    for (int dy = 0; dy < 32; dy += 8) {
        const int n = n0 + ty + dy, k = k0 + tx;
        const float v = t[tx][ty + dy];
        const __nv_bfloat16 hi = __float2bfloat16(v);
        const __nv_bfloat16 lo = __float2bfloat16(v - __bfloat162float(hi));
        __nv_bfloat16* Br = Bt + (long)n * KSPLIT;
        Br[k]           = hi;
        Br[k + DIN]     = lo;
        Br[k + 2 * DIN] = hi;
    }
}

// ---------------------------------------------------------------------------
// GEMM1, split-K=2. B operand now via ldsm_x4 (halves B LDSM issue count).
// ---------------------------------------------------------------------------
__global__ void __launch_bounds__(256, 2)
gemm_tc(const __nv_bfloat16* __restrict__ Ag, const __nv_bfloat16* __restrict__ Bg,
        float* __restrict__ Cbase)
{
    extern __shared__ char dynsmem[];

    const int tid  = threadIdx.x;
    const int warp = tid >> 5, lane = tid & 31;
    const int wm = warp >> 2;
    const int wn = warp & 3;
    const int bn = blockIdx.x, bm = blockIdx.y, kz = blockIdx.z;

    const uint32_t abase = (smem_u32(dynsmem) + 1023u) & ~1023u;

    const __nv_bfloat16* Atile = Ag + (long)(bm * 128) * KSPLIT;
    const __nv_bfloat16* Btile = Bg + (long)(bn * 128) * KSPLIT;
    float* C = Cbase + (long)kz * (B_SZ * DOUT);
    const int kbase = kz * (NCHH * KC);

    auto load_chunk = [&](int c, int s) {
        const uint32_t sa = abase + s * STAGEB;
        const uint32_t sb = sa + TILEB;
        const int koff = kbase + c * KC;
        #pragma unroll
        for (int it = 0; it < 4; it++) {
            const int idx = it * 256 + tid;
            const int row = idx >> 3;
            const int c16 = idx & 7;
            const uint32_t soff = swz(row * 128 + c16 * 16);
            cpasync16(sa + soff, Atile + (long)row * KSPLIT + koff + c16 * 8);
            cpasync16(sb + soff, Btile + (long)row * KSPLIT + koff + c16 * 8);
        }
        asm volatile("cp.async.commit_group;" ::: "memory");
    };

    float acc[4][4][4];
    #pragma unroll
    for (int mt = 0; mt < 4; mt++)
        #pragma unroll
        for (int nt = 0; nt < 4; nt++)
            #pragma unroll
            for (int j = 0; j < 4; j++) acc[mt][nt][j] = 0.f;

    const uint32_t a_row = wm * 64 + (lane & 15);
    const uint32_t a_seg = (lane >> 4) * 16;
    // B x4 addressing: lanes 0-7 -> (n0-7,k0-7), 8-15 -> (n0-7,k8-15),
    //                  16-23 -> (n8-15,k0-7), 24-31 -> (n8-15,k8-15)
    const uint32_t b_row4 = wn * 32 + (lane & 7) + ((lane >> 4) << 3);
    const uint32_t b_seg4 = ((lane >> 3) & 1) * 16;

    load_chunk(0, 0);
    load_chunk(1, 1);

    int s_cons = 0, s_load = 2;
    for (int c = 0; c < NCHH; c++) {
        asm volatile("cp.async.wait_group %0;" :: "n"(GS - 2) : "memory");
        __syncthreads();

        const int nl = c + GS - 1;
        if (nl < NCHH) load_chunk(nl, s_load);
        if (++s_load == GS) s_load = 0;

        const uint32_t sa = abase + s_cons * STAGEB;
        const uint32_t sb = sa + TILEB;
        if (++s_cons == GS) s_cons = 0;

        #pragma unroll
        for (int ks = 0; ks < 4; ks++) {
            uint32_t bf[2][4];
            ldsm_x4(bf[0], sb + swz((b_row4)      * 128 + ks * 32 + b_seg4));
            ldsm_x4(bf[1], sb + swz((b_row4 + 16) * 128 + ks * 32 + b_seg4));
            #pragma unroll
            for (int mt = 0; mt < 4; mt++) {
                uint32_t af[4];
                ldsm_x4(af, sa + swz((a_row + mt * 16) * 128 + ks * 32 + a_seg));
                mma16816(acc[mt][0], af, &bf[0][0]);
                mma16816(acc[mt][1], af, &bf[0][2]);
                mma16816(acc[mt][2], af, &bf[1][0]);
                mma16816(acc[mt][3], af, &bf[1][2]);
            }
        }
    }

    const int g  = lane >> 2;
    const int tg = lane & 3;
    #pragma unroll
    for (int mt = 0; mt < 4; mt++) {
        const int m = bm * 128 + wm * 64 + mt * 16 + g;
        #pragma unroll
        for (int nt = 0; nt < 4; nt++) {
            const int n = bn * 128 + wn * 32 + nt * 8 + 2 * tg;
            float2 v0, v1;
            v0.x = acc[mt][nt][0];  v0.y = acc[mt][nt][1];
            v1.x = acc[mt][nt][2];  v1.y = acc[mt][nt][3];
            *(float2*)(C + (long)m * DOUT + n)       = v0;
            *(float2*)(C + (long)(m + 8) * DOUT + n) = v1;
        }
    }
}

// ---------------------------------------------------------------------------
// Kernel 2: ROWS=4 (1024 CTAs) fused pipeline, packed f32x2 in B and E.
// Stage B: 2 warps per row, each covers half the d-range.
// ---------------------------------------------------------------------------
#define ROWS 4

__global__ void __launch_bounds__(256)
kan_fused(const float* __restrict__ xp0, const float* __restrict__ xp1,
          const float* __restrict__ bp,
          const float* __restrict__ wi1, const float* __restrict__ bi1,
          const float* __restrict__ wi2, const float* __restrict__ bi2,
          const float* __restrict__ wo1, const float* __restrict__ bo1,
          const float* __restrict__ wo2, const float* __restrict__ bo2,
          const float* __restrict__ gamma, const float* __restrict__ beta,
          float* __restrict__ out)
{
    __shared__ float rows[ROWS][DOUT];       // 8 KB
    __shared__ float Ssh[2][ROWS][H1_SZ];    // half-sums
    __shared__ float ush[ROWS][Q_SZ];
    __shared__ float GshT[H2_SZ][8];         // [h2][r], padded to 8
    __shared__ float red[ROWS][8][2];

    const int tid  = threadIdx.x;
    const int warp = tid >> 5;
    const int lane = tid & 31;
    const long base = (long)blockIdx.x * ROWS * DOUT;

    // Load 4 rows: xp0 + xp1 + bias  (512 float4, 2 iters)
    {
        const float4* s0 = (const float4*)(xp0 + base);
        const float4* s1 = (const float4*)(xp1 + base);
        const float4* bb = (const float4*)bp;
        float4* dst = (float4*)(&rows[0][0]);
        #pragma unroll
        for (int i = 0; i < 2; i++) {
            const int j = tid + i * 256;
            const float4 a = s0[j];
            const float4 b = s1[j];
            const float4 c = bb[j & 127];
            float4 o;
            o.x = a.x + b.x + c.x;
            o.y = a.y + b.y + c.y;
            o.z = a.z + b.z + c.z;
            o.w = a.w + b.w + c.w;
            dst[j] = o;
        }
    }
    __syncthreads();

    // Stage B: warp -> (row = w>>1, half = w&1); half covers 256 d's.
    {
        const int r = warp >> 1, half = warp & 1;
        const float4* rv = (const float4*)(&rows[r][0]) + half * 64;

        // half-row sum V
        uint64_t vp = pk2(0.f, 0.f);
        #pragma unroll
        for (int i = 0; i < 2; i++) {
            const float4 v = rv[lane + i * 32];
            vp = add2(vp, pk2(v.x, v.y));
            vp = add2(vp, pk2(v.z, v.w));
        }
        float va, vb; upk2(vp, va, vb);
        float vs = va + vb;
        #pragma unroll
        for (int off = 16; off > 0; off >>= 1)
            vs += __shfl_xor_sync(0xffffffffu, vs, off);

        const float w1 = wi1[lane];
        const float b1 = bi1[lane];
        const uint64_t w11 = pk2(w1, w1);
        const uint64_t b11 = pk2(b1, b1);
        uint64_t s01 = pk2(0.f, 0.f), s23 = pk2(0.f, 0.f);
        #pragma unroll 4
        for (int d4 = 0; d4 < 64; d4++) {
            const float4 v = rv[d4];
            s01 = add2(s01, abs2(fma2(pk2(v.x, v.y), w11, b11)));
            s23 = add2(s23, abs2(fma2(pk2(v.z, v.w), w11, b11)));
        }
        float a0, a1, a2, a3;
        upk2(s01, a0, a1); upk2(s23, a2, a3);
        const float sabs = (a0 + a1) + (a2 + a3);
        // half contribution: 0.5*(w*Vh + 256*b + sum|.|_h); halves sum to full S
        Ssh[half][r][lane] = 0.5f * (fmaf(w1, vs, 256.0f * b1) + sabs);
    }
    __syncthreads();

    // Stage C: one iteration, thread -> (r, q)
    {
        const int r = tid >> 6, q = tid & 63;
        float acc = (float)DOUT * bi2[q];
        #pragma unroll
        for (int h = 0; h < H1_SZ; h++)
            acc = fmaf(Ssh[0][r][h] + Ssh[1][r][h], wi2[h * Q_SZ + q], acc);
        ush[r][q] = acc;
    }
    __syncthreads();

    // Stage D: one iteration, thread -> (r, h2); store transposed
    {
        const int r = tid >> 6, h2 = tid & 63;
        const float w = wo1[h2];
        const float b = bo1[h2];
        float g = 0.f;
        #pragma unroll
        for (int q = 0; q < Q_SZ; q++)
            g += fmaxf(fmaf(ush[r][q], w, b), 0.f);
        GshT[h2][r] = g;
    }
    __syncthreads();

    // Stage E (packed): 2 cols/thread, rows packed in pairs
    const int d0 = tid * 2;
    uint64_t acc2[4];
    #pragma unroll
    for (int j = 0; j < 4; j++) acc2[j] = pk2(0.f, 0.f);

    #pragma unroll 4
    for (int h2 = 0; h2 < H2_SZ; h2++) {
        const float2 w = *(const float2*)(wo2 + h2 * DOUT + d0);   // LDG.64
        const float4 ga = *(const float4*)(&GshT[h2][0]);          // rows 0-3, bcast
        const uint64_t wx  = pk2(w.x, w.x);
        const uint64_t wy  = pk2(w.y, w.y);
        const uint64_t g01 = pk2(ga.x, ga.y);
        const uint64_t g23 = pk2(ga.z, ga.w);
        acc2[0] = fma2(g01, wx, acc2[0]);
        acc2[1] = fma2(g23, wx, acc2[1]);
        acc2[2] = fma2(g01, wy, acc2[2]);
        acc2[3] = fma2(g23, wy, acc2[3]);
    }

    float ax[ROWS], ay[ROWS];
    {
        const float2 bo = *(const float2*)(bo2 + d0);
        const uint64_t bbx = pk2((float)Q_SZ * bo.x, (float)Q_SZ * bo.x);
        const uint64_t bby = pk2((float)Q_SZ * bo.y, (float)Q_SZ * bo.y);
        acc2[0] = add2(acc2[0], bbx);
        acc2[1] = add2(acc2[1], bbx);
        acc2[2] = add2(acc2[2], bby);
        acc2[3] = add2(acc2[3], bby);
        upk2(acc2[0], ax[0], ax[1]);
        upk2(acc2[1], ax[2], ax[3]);
        upk2(acc2[2], ay[0], ay[1]);
        upk2(acc2[3], ay[2], ay[3]);
    }

    // LayerNorm reductions
    #pragma unroll
    for (int r = 0; r < ROWS; r++) {
        float ps = ax[r] + ay[r];
        float pq = ax[r] * ax[r] + ay[r] * ay[r];
        #pragma unroll
        for (int off = 16; off > 0; off >>= 1) {
            ps += __shfl_xor_sync(0xffffffffu, ps, off);
            pq += __shfl_xor_sync(0xffffffffu, pq, off);
        }
        if (lane == 0) { red[r][warp][0] = ps; red[r][warp][1] = pq; }
    }
    __syncthreads();

    const float2 gm = *(const float2*)(gamma + d0);
    const float2 bt = *(const float2*)(beta + d0);
    #pragma unroll
    for (int r = 0; r < ROWS; r++) {
        float s = 0.f, q2 = 0.f;
        #pragma unroll
        for (int w = 0; w < 8; w++) { s += red[r][w][0]; q2 += red[r][w][1]; }
        const float mu  = s * (1.f / (float)DOUT);
        const float var = q2 * (1.f / (float)DOUT) - mu * mu;
        const float inv = rsqrtf(var + EPS);
        float2 o;
        o.x = (ax[r] - mu) * inv * gm.x + bt.x;
        o.y = (ay[r] - mu) * inv * gm.y + bt.y;
        *(float2*)(out + base + (long)r * DOUT + d0) = o;
    }
}

// ---------------------------------------------------------------------------
// Launch
// ---------------------------------------------------------------------------
extern "C" void kernel_launch(void* const* d_in, const int* in_sizes, int n_in,
                              void* d_out, int out_size)
{
    const float* x     = (const float*)d_in[0];
    const float* wp    = (const float*)d_in[1];
    const float* bp    = (const float*)d_in[2];
    const float* wi1   = (const float*)d_in[3];
    const float* bi1   = (const float*)d_in[4];
    const float* wi2   = (const float*)d_in[5];
    const float* bi2   = (const float*)d_in[6];
    const float* wo1   = (const float*)d_in[7];
    const float* bo1   = (const float*)d_in[8];
    const float* wo2   = (const float*)d_in[9];
    const float* bo2   = (const float*)d_in[10];
    const float* gamma = (const float*)d_in[11];
    const float* beta  = (const float*)d_in[12];
    float* out = (float*)d_out;

    float* xp;             cudaGetSymbolAddress((void**)&xp, g_xp);
    __nv_bfloat16* Ab;     cudaGetSymbolAddress((void**)&Ab, g_A);
    __nv_bfloat16* Bb;     cudaGetSymbolAddress((void**)&Bb, g_Bt);

    conv_x<<<B_SZ, 256>>>(x, Ab);
    conv_w<<<dim3(DIN / 32, DOUT / 32), 256>>>(wp, Bb);

    const int dyn = GS * STAGEB + 1024;   // ~97 KB
    cudaFuncSetAttribute(gemm_tc, cudaFuncAttributeMaxDynamicSharedMemorySize, dyn);
    gemm_tc<<<dim3(DOUT / 128, B_SZ / 128, 2), 256, dyn>>>(Ab, Bb, xp);

    kan_fused<<<B_SZ / ROWS, 256>>>(xp, xp + (long)B_SZ * DOUT, bp,
                                    wi1, bi1, wi2, bi2,
                                    wo1, bo1, wo2, bo2, gamma, beta, out);
}

// round 9
// speedup vs baseline: 1.0303x; 1.0303x over previous
#include <cuda_runtime.h>
#include <cuda_bf16.h>
#include <cstdint>

// Problem constants
#define B_SZ   4096
#define DIN    768
#define DOUT   512
#define Q_SZ   64
#define H1_SZ  32
#define H2_SZ  64
#define EPS    1e-5f

// GEMM1 split-K: K' = 3 * DIN, split across 2 CTAs in z
#define KSPLIT (3 * DIN)          // 2304
#define KC     64
#define NCHH   (KSPLIT / KC / 2)  // 18 chunks per K-half
#define GS     3                  // pipeline stages
#define TILEB  16384              // one 128x64 bf16 tile
#define STAGEB (2 * TILEB)

// ---------------------------------------------------------------------------
// Static device scratch
// ---------------------------------------------------------------------------
__device__ __align__(256) float          g_xp[2][B_SZ * DOUT];          // 16 MB partials
__device__ __align__(256) __nv_bfloat16  g_A[B_SZ * KSPLIT];            // 18.9 MB
__device__ __align__(256) __nv_bfloat16  g_Bt[DOUT * KSPLIT];           // 2.36 MB

// ---------------------------------------------------------------------------
// Helpers
// ---------------------------------------------------------------------------
__device__ __forceinline__ uint32_t smem_u32(const void* p) {
    uint32_t a;
    asm("{ .reg .u64 t; cvta.to.shared.u64 t, %1; cvt.u32.u64 %0, t; }"
        : "=r"(a) : "l"(p));
    return a;
}
__device__ __forceinline__ uint32_t swz(uint32_t off) {
    return off ^ ((off >> 3) & 0x70);
}
__device__ __forceinline__ void cpasync16(uint32_t dst, const void* src) {
    asm volatile("cp.async.cg.shared.global [%0], [%1], 16;"
                 :: "r"(dst), "l"(src) : "memory");
}
__device__ __forceinline__ void ldsm_x4(uint32_t* r, uint32_t addr) {
    asm volatile("ldmatrix.sync.aligned.m8n8.x4.shared.b16 {%0,%1,%2,%3}, [%4];"
                 : "=r"(r[0]), "=r"(r[1]), "=r"(r[2]), "=r"(r[3]) : "r"(addr));
}
__device__ __forceinline__ void mma16816(float* d, const uint32_t* a, const uint32_t* b) {
    asm volatile(
        "mma.sync.aligned.m16n8k16.row.col.f32.bf16.bf16.f32 "
        "{%0,%1,%2,%3}, {%4,%5,%6,%7}, {%8,%9}, {%0,%1,%2,%3};"
        : "+f"(d[0]), "+f"(d[1]), "+f"(d[2]), "+f"(d[3])
        : "r"(a[0]), "r"(a[1]), "r"(a[2]), "r"(a[3]), "r"(b[0]), "r"(b[1]));
}

// ---- packed f32x2 ----
__device__ __forceinline__ uint64_t pk2(float x, float y) {
    uint64_t r; asm("mov.b64 %0,{%1,%2};" : "=l"(r) : "f"(x), "f"(y)); return r;
}
__device__ __forceinline__ void upk2(uint64_t v, float& x, float& y) {
    asm("mov.b64 {%0,%1},%2;" : "=f"(x), "=f"(y) : "l"(v));
}
__device__ __forceinline__ uint64_t fma2(uint64_t a, uint64_t b, uint64_t c) {
    uint64_t d; asm("fma.rn.f32x2 %0,%1,%2,%3;" : "=l"(d) : "l"(a), "l"(b), "l"(c));
    return d;
}
__device__ __forceinline__ uint64_t add2(uint64_t a, uint64_t b) {
    uint64_t d; asm("add.rn.f32x2 %0,%1,%2;" : "=l"(d) : "l"(a), "l"(b));
    return d;
}
__device__ __forceinline__ uint64_t abs2(uint64_t a) {
    uint64_t d; asm("and.b64 %0,%1,0x7FFFFFFF7FFFFFFF;" : "=l"(d) : "l"(a));
    return d;
}

// ---------------------------------------------------------------------------
// Conversions (fp32 -> bf16 hi/lo, 3-term fold into K)
// ---------------------------------------------------------------------------
__global__ void __launch_bounds__(256)
conv_x(const float* __restrict__ x, __nv_bfloat16* __restrict__ A)
{
    const int row = blockIdx.x;
    const float* xr = x + (long)row * DIN;
    __nv_bfloat16* Ar = A + (long)row * KSPLIT;
    #pragma unroll
    for (int i = 0; i < 3; i++) {
        const int k = threadIdx.x + i * 256;
        const float v = xr[k];
        const __nv_bfloat16 hi = __float2bfloat16(v);
        const __nv_bfloat16 lo = __float2bfloat16(v - __bfloat162float(hi));
        Ar[k]            = hi;
        Ar[k + DIN]      = hi;
        Ar[k + 2 * DIN]  = lo;
    }
}

__global__ void __launch_bounds__(256)
conv_w(const float* __restrict__ wp, __nv_bfloat16* __restrict__ Bt)
{
    __shared__ float t[32][33];
    const int k0 = blockIdx.x * 32, n0 = blockIdx.y * 32;
    const int tx = threadIdx.x & 31;
    const int ty = threadIdx.x >> 5;
    #pragma unroll
    for (int dy = 0; dy < 32; dy += 8)
        t[ty + dy][tx] = wp[(long)(k0 + ty + dy) * DOUT + n0 + tx];
    __syncthreads();
    #pragma unroll
    for (int dy = 0; dy < 32; dy += 8) {
        const int n = n0 + ty + dy, k = k0 + tx;
        const float v = t[tx][ty + dy];
        const __nv_bfloat16 hi = __float2bfloat16(v);
        const __nv_bfloat16 lo = __float2bfloat16(v - __bfloat162float(hi));
        __nv_bfloat16* Br = Bt + (long)n * KSPLIT;
        Br[k]           = hi;
        Br[k + DIN]     = lo;
        Br[k + 2 * DIN] = hi;
    }
}

// ---------------------------------------------------------------------------
// GEMM1, split-K=2 (unchanged from R8)
// ---------------------------------------------------------------------------
__global__ void __launch_bounds__(256, 2)
gemm_tc(const __nv_bfloat16* __restrict__ Ag, const __nv_bfloat16* __restrict__ Bg,
        float* __restrict__ Cbase)
{
    extern __shared__ char dynsmem[];

    const int tid  = threadIdx.x;
    const int warp = tid >> 5, lane = tid & 31;
    const int wm = warp >> 2;
    const int wn = warp & 3;
    const int bn = blockIdx.x, bm = blockIdx.y, kz = blockIdx.z;

    const uint32_t abase = (smem_u32(dynsmem) + 1023u) & ~1023u;

    const __nv_bfloat16* Atile = Ag + (long)(bm * 128) * KSPLIT;
    const __nv_bfloat16* Btile = Bg + (long)(bn * 128) * KSPLIT;
    float* C = Cbase + (long)kz * (B_SZ * DOUT);
    const int kbase = kz * (NCHH * KC);

    auto load_chunk = [&](int c, int s) {
        const uint32_t sa = abase + s * STAGEB;
        const uint32_t sb = sa + TILEB;
        const int koff = kbase + c * KC;
        #pragma unroll
        for (int it = 0; it < 4; it++) {
            const int idx = it * 256 + tid;
            const int row = idx >> 3;
            const int c16 = idx & 7;
            const uint32_t soff = swz(row * 128 + c16 * 16);
            cpasync16(sa + soff, Atile + (long)row * KSPLIT + koff + c16 * 8);
            cpasync16(sb + soff, Btile + (long)row * KSPLIT + koff + c16 * 8);
        }
        asm volatile("cp.async.commit_group;" ::: "memory");
    };

    float acc[4][4][4];
    #pragma unroll
    for (int mt = 0; mt < 4; mt++)
        #pragma unroll
        for (int nt = 0; nt < 4; nt++)
            #pragma unroll
            for (int j = 0; j < 4; j++) acc[mt][nt][j] = 0.f;

    const uint32_t a_row = wm * 64 + (lane & 15);
    const uint32_t a_seg = (lane >> 4) * 16;
    const uint32_t b_row4 = wn * 32 + (lane & 7) + ((lane >> 4) << 3);
    const uint32_t b_seg4 = ((lane >> 3) & 1) * 16;

    load_chunk(0, 0);
    load_chunk(1, 1);

    int s_cons = 0, s_load = 2;
    for (int c = 0; c < NCHH; c++) {
        asm volatile("cp.async.wait_group %0;" :: "n"(GS - 2) : "memory");
        __syncthreads();

        const int nl = c + GS - 1;
        if (nl < NCHH) load_chunk(nl, s_load);
        if (++s_load == GS) s_load = 0;

        const uint32_t sa = abase + s_cons * STAGEB;
        const uint32_t sb = sa + TILEB;
        if (++s_cons == GS) s_cons = 0;

        #pragma unroll
        for (int ks = 0; ks < 4; ks++) {
            uint32_t bf[2][4];
            ldsm_x4(bf[0], sb + swz((b_row4)      * 128 + ks * 32 + b_seg4));
            ldsm_x4(bf[1], sb + swz((b_row4 + 16) * 128 + ks * 32 + b_seg4));
            #pragma unroll
            for (int mt = 0; mt < 4; mt++) {
                uint32_t af[4];
                ldsm_x4(af, sa + swz((a_row + mt * 16) * 128 + ks * 32 + a_seg));
                mma16816(acc[mt][0], af, &bf[0][0]);
                mma16816(acc[mt][1], af, &bf[0][2]);
                mma16816(acc[mt][2], af, &bf[1][0]);
                mma16816(acc[mt][3], af, &bf[1][2]);
            }
        }
    }

    const int g  = lane >> 2;
    const int tg = lane & 3;
    #pragma unroll
    for (int mt = 0; mt < 4; mt++) {
        const int m = bm * 128 + wm * 64 + mt * 16 + g;
        #pragma unroll
        for (int nt = 0; nt < 4; nt++) {
            const int n = bn * 128 + wn * 32 + nt * 8 + 2 * tg;
            float2 v0, v1;
            v0.x = acc[mt][nt][0];  v0.y = acc[mt][nt][1];
            v1.x = acc[mt][nt][2];  v1.y = acc[mt][nt][3];
            *(float2*)(C + (long)m * DOUT + n)       = v0;
            *(float2*)(C + (long)(m + 8) * DOUT + n) = v1;
        }
    }
}

// ---------------------------------------------------------------------------
// Kernel 2: ROWS=16, 256 threads, grid=256. Amortizes per-CTA weight re-reads.
// ---------------------------------------------------------------------------
#define ROWS 16

__global__ void __launch_bounds__(256)
kan_fused(const float* __restrict__ xp0, const float* __restrict__ xp1,
          const float* __restrict__ bp,
          const float* __restrict__ wi1, const float* __restrict__ bi1,
          const float* __restrict__ wi2, const float* __restrict__ bi2,
          const float* __restrict__ wo1, const float* __restrict__ bo1,
          const float* __restrict__ wo2, const float* __restrict__ bo2,
          const float* __restrict__ gamma, const float* __restrict__ beta,
          float* __restrict__ out)
{
    __shared__ float rows[ROWS][DOUT];       // 32 KB
    __shared__ float Ssh[ROWS][H1_SZ];       // 2 KB
    __shared__ float ush[ROWS][Q_SZ];        // 4 KB
    __shared__ float GshT[H2_SZ][20];        // 5 KB, padded: float4-aligned rows
    __shared__ float red[ROWS][8][2];        // 1 KB
    __shared__ float muS[ROWS], invS[ROWS];

    const int tid  = threadIdx.x;
    const int warp = tid >> 5;
    const int lane = tid & 31;
    const long base = (long)blockIdx.x * ROWS * DOUT;

    // Load 16 rows: xp0 + xp1 + bias  (2048 float4 per source)
    {
        const float4* s0 = (const float4*)(xp0 + base);
        const float4* s1 = (const float4*)(xp1 + base);
        const float4* bb = (const float4*)bp;
        float4* dst = (float4*)(&rows[0][0]);
        #pragma unroll
        for (int i = 0; i < 8; i++) {
            const int j = tid + i * 256;
            const float4 a = s0[j];
            const float4 b = s1[j];
            const float4 c = bb[j & 127];
            float4 o;
            o.x = a.x + b.x + c.x;
            o.y = a.y + b.y + c.y;
            o.z = a.z + b.z + c.z;
            o.w = a.w + b.w + c.w;
            dst[j] = o;
        }
    }
    __syncthreads();

    // Stage B: warp owns rows 2w, 2w+1; lane = h. S = 0.5*(w*V + 512b + sum|t|)
    {
        const int r0 = 2 * warp, r1 = r0 + 1;
        const float4* rva = (const float4*)(&rows[r0][0]);
        const float4* rvb = (const float4*)(&rows[r1][0]);

        uint64_t vpa = pk2(0.f, 0.f), vpb = pk2(0.f, 0.f);
        #pragma unroll
        for (int i = 0; i < 4; i++) {
            const float4 a = rva[lane + i * 32];
            const float4 b = rvb[lane + i * 32];
            vpa = add2(vpa, pk2(a.x, a.y));  vpa = add2(vpa, pk2(a.z, a.w));
            vpb = add2(vpb, pk2(b.x, b.y));  vpb = add2(vpb, pk2(b.z, b.w));
        }
        float t0, t1;
        upk2(vpa, t0, t1);  float vsa = t0 + t1;
        upk2(vpb, t0, t1);  float vsb = t0 + t1;
        #pragma unroll
        for (int off = 16; off > 0; off >>= 1) {
            vsa += __shfl_xor_sync(0xffffffffu, vsa, off);
            vsb += __shfl_xor_sync(0xffffffffu, vsb, off);
        }

        const float w1 = wi1[lane];
        const float b1 = bi1[lane];
        const uint64_t w11 = pk2(w1, w1);
        const uint64_t b11 = pk2(b1, b1);
        uint64_t sa0 = pk2(0.f, 0.f), sa1 = pk2(0.f, 0.f);
        uint64_t sb0 = pk2(0.f, 0.f), sb1 = pk2(0.f, 0.f);
        #pragma unroll 4
        for (int d4 = 0; d4 < DOUT / 4; d4++) {
            const float4 a = rva[d4];
            const float4 b = rvb[d4];
            sa0 = add2(sa0, abs2(fma2(pk2(a.x, a.y), w11, b11)));
            sa1 = add2(sa1, abs2(fma2(pk2(a.z, a.w), w11, b11)));
            sb0 = add2(sb0, abs2(fma2(pk2(b.x, b.y), w11, b11)));
            sb1 = add2(sb1, abs2(fma2(pk2(b.z, b.w), w11, b11)));
        }
        float a0, a1, a2, a3;
        upk2(sa0, a0, a1); upk2(sa1, a2, a3);
        const float sabsa = (a0 + a1) + (a2 + a3);
        upk2(sb0, a0, a1); upk2(sb1, a2, a3);
        const float sabsb = (a0 + a1) + (a2 + a3);
        Ssh[r0][lane] = 0.5f * (fmaf(w1, vsa, (float)DOUT * b1) + sabsa);
        Ssh[r1][lane] = 0.5f * (fmaf(w1, vsb, (float)DOUT * b1) + sabsb);
    }
    __syncthreads();

    // Stage C: f32x2 over q-pairs. idx -> (r = idx>>5 uniform/warp, qp = lane)
    #pragma unroll
    for (int it = 0; it < 2; it++) {
        const int idx = tid + it * 256;
        const int r = idx >> 5;
        const int q0 = (idx & 31) * 2;
        const float2 bi = *(const float2*)(bi2 + q0);
        uint64_t acc = pk2((float)DOUT * bi.x, (float)DOUT * bi.y);
        #pragma unroll
        for (int h = 0; h < H1_SZ; h++) {
            const float s = Ssh[r][h];                       // uniform LDS
            const float2 w2 = *(const float2*)(wi2 + h * Q_SZ + q0);
            acc = fma2(pk2(s, s), pk2(w2.x, w2.y), acc);
        }
        float ux, uy; upk2(acc, ux, uy);
        *(float2*)(&ush[r][q0]) = make_float2(ux, uy);
    }
    __syncthreads();

    // Stage D: scalar; r uniform per warp; store GshT[h2][r] (pad 20)
    #pragma unroll
    for (int it = 0; it < 4; it++) {
        const int idx = tid + it * 256;
        const int r = idx >> 6;
        const int h2 = idx & 63;
        const float w = wo1[h2];
        const float b = bo1[h2];
        float g = 0.f;
        #pragma unroll
        for (int q = 0; q < Q_SZ; q++)
            g += fmaxf(fmaf(ush[r][q], w, b), 0.f);          // uniform LDS
        GshT[h2][r] = g;
    }
    __syncthreads();

    // Stage E: 2 cols/thread, 16 rows in packed pairs. Per h2:
    // 1 LDG.64 + 4 uniform LDS.128 + 16 FFMA2.
    const int d0 = tid * 2;
    uint64_t accx[8], accy[8];
    #pragma unroll
    for (int p = 0; p < 8; p++) { accx[p] = pk2(0.f, 0.f); accy[p] = pk2(0.f, 0.f); }

    #pragma unroll 2
    for (int h2 = 0; h2 < H2_SZ; h2++) {
        const float2 w = *(const float2*)(wo2 + h2 * DOUT + d0);
        const float4* gp = (const float4*)(&GshT[h2][0]);
        const float4 g0 = gp[0], g1 = gp[1], g2 = gp[2], g3 = gp[3];
        const uint64_t wx = pk2(w.x, w.x);
        const uint64_t wy = pk2(w.y, w.y);
        const uint64_t q0 = pk2(g0.x, g0.y), q1 = pk2(g0.z, g0.w);
        const uint64_t q2 = pk2(g1.x, g1.y), q3 = pk2(g1.z, g1.w);
        const uint64_t q4 = pk2(g2.x, g2.y), q5 = pk2(g2.z, g2.w);
        const uint64_t q6 = pk2(g3.x, g3.y), q7 = pk2(g3.z, g3.w);
        accx[0] = fma2(q0, wx, accx[0]);  accy[0] = fma2(q0, wy, accy[0]);
        accx[1] = fma2(q1, wx, accx[1]);  accy[1] = fma2(q1, wy, accy[1]);
        accx[2] = fma2(q2, wx, accx[2]);  accy[2] = fma2(q2, wy, accy[2]);
        accx[3] = fma2(q3, wx, accx[3]);  accy[3] = fma2(q3, wy, accy[3]);
        accx[4] = fma2(q4, wx, accx[4]);  accy[4] = fma2(q4, wy, accy[4]);
        accx[5] = fma2(q5, wx, accx[5]);  accy[5] = fma2(q5, wy, accy[5]);
        accx[6] = fma2(q6, wx, accx[6]);  accy[6] = fma2(q6, wy, accy[6]);
        accx[7] = fma2(q7, wx, accx[7]);  accy[7] = fma2(q7, wy, accy[7]);
    }
    {
        const float2 bo = *(const float2*)(bo2 + d0);
        const uint64_t bbx = pk2((float)Q_SZ * bo.x, (float)Q_SZ * bo.x);
        const uint64_t bby = pk2((float)Q_SZ * bo.y, (float)Q_SZ * bo.y);
        #pragma unroll
        for (int p = 0; p < 8; p++) {
            accx[p] = add2(accx[p], bbx);
            accy[p] = add2(accy[p], bby);
        }
    }

    // LayerNorm: per-row (sum, sumsq) shfl reduce -> red -> muS/invS
    #pragma unroll
    for (int p = 0; p < 8; p++) {
        float x0, x1, y0, y1;
        upk2(accx[p], x0, x1);
        upk2(accy[p], y0, y1);
        float ps0 = x0 + y0, pq0 = x0 * x0 + y0 * y0;
        float ps1 = x1 + y1, pq1 = x1 * x1 + y1 * y1;
        #pragma unroll
        for (int off = 16; off > 0; off >>= 1) {
            ps0 += __shfl_xor_sync(0xffffffffu, ps0, off);
            pq0 += __shfl_xor_sync(0xffffffffu, pq0, off);
            ps1 += __shfl_xor_sync(0xffffffffu, ps1, off);
            pq1 += __shfl_xor_sync(0xffffffffu, pq1, off);
        }
        if (lane == 0) {
            red[2 * p][warp][0]     = ps0;  red[2 * p][warp][1]     = pq0;
            red[2 * p + 1][warp][0] = ps1;  red[2 * p + 1][warp][1] = pq1;
        }
    }
    __syncthreads();

    if (tid < ROWS) {
        float s = 0.f, q2 = 0.f;
        #pragma unroll
        for (int w = 0; w < 8; w++) { s += red[tid][w][0]; q2 += red[tid][w][1]; }
        const float mu  = s * (1.f / (float)DOUT);
        const float var = q2 * (1.f / (float)DOUT) - mu * mu;
        muS[tid]  = mu;
        invS[tid] = rsqrtf(var + EPS);
    }
    __syncthreads();

    const float2 gm = *(const float2*)(gamma + d0);
    const float2 bt = *(const float2*)(beta + d0);
    #pragma unroll
    for (int p = 0; p < 8; p++) {
        float x0, x1, y0, y1;
        upk2(accx[p], x0, x1);
        upk2(accy[p], y0, y1);
        const int r0 = 2 * p, r1 = 2 * p + 1;
        float2 o0, o1;
        o0.x = (x0 - muS[r0]) * invS[r0] * gm.x + bt.x;
        o0.y = (y0 - muS[r0]) * invS[r0] * gm.y + bt.y;
        o1.x = (x1 - muS[r1]) * invS[r1] * gm.x + bt.x;
        o1.y = (y1 - muS[r1]) * invS[r1] * gm.y + bt.y;
        *(float2*)(out + base + (long)r0 * DOUT + d0) = o0;
        *(float2*)(out + base + (long)r1 * DOUT + d0) = o1;
    }
}

// ---------------------------------------------------------------------------
// Launch
// ---------------------------------------------------------------------------
extern "C" void kernel_launch(void* const* d_in, const int* in_sizes, int n_in,
                              void* d_out, int out_size)
{
    const float* x     = (const float*)d_in[0];
    const float* wp    = (const float*)d_in[1];
    const float* bp    = (const float*)d_in[2];
    const float* wi1   = (const float*)d_in[3];
    const float* bi1   = (const float*)d_in[4];
    const float* wi2   = (const float*)d_in[5];
    const float* bi2   = (const float*)d_in[6];
    const float* wo1   = (const float*)d_in[7];
    const float* bo1   = (const float*)d_in[8];
    const float* wo2   = (const float*)d_in[9];
    const float* bo2   = (const float*)d_in[10];
    const float* gamma = (const float*)d_in[11];
    const float* beta  = (const float*)d_in[12];
    float* out = (float*)d_out;

    float* xp;             cudaGetSymbolAddress((void**)&xp, g_xp);
    __nv_bfloat16* Ab;     cudaGetSymbolAddress((void**)&Ab, g_A);
    __nv_bfloat16* Bb;     cudaGetSymbolAddress((void**)&Bb, g_Bt);

    conv_x<<<B_SZ, 256>>>(x, Ab);
    conv_w<<<dim3(DIN / 32, DOUT / 32), 256>>>(wp, Bb);

    const int dyn = GS * STAGEB + 1024;   // ~97 KB
    cudaFuncSetAttribute(gemm_tc, cudaFuncAttributeMaxDynamicSharedMemorySize, dyn);
    gemm_tc<<<dim3(DOUT / 128, B_SZ / 128, 2), 256, dyn>>>(Ab, Bb, xp);

    kan_fused<<<B_SZ / ROWS, 256>>>(xp, xp + (long)B_SZ * DOUT, bp,
                                    wi1, bi1, wi2, bi2,
                                    wo1, bo1, wo2, bo2, gamma, beta, out);
}